// round 1
// baseline (speedup 1.0000x reference)
#include <cuda_runtime.h>

#define BATCH      131072
#define HID        256
#define SPIKE_DIM  128
#define COORD_DIM  64
#define IN_DIM     192
#define NUM_STEPS  25
#define BETA       0.7f
#define OMB        (1.0f - BETA)   // 0.30000001192092896f, matches fp32 1.0-0.7

// ---------------- device scratch (static; no runtime allocation) ----------------
__device__ float    g_c0[(size_t)BATCH * HID];     // only written for heavy rows
__device__ int      g_flags[BATCH];
__device__ float    g_W1T[HID * HID];              // W1T[j][i] = W1[i][j]
__device__ float    g_WcT[HID * COORD_DIM];        // WcT[i][m] = W_out[128+m][i]
__device__ unsigned g_wmax_u, g_bmax_u;
__device__ int      g_Hlim;

// ---------------- prep ----------------
__global__ void k_init() { g_wmax_u = 0u; g_bmax_u = 0u; }

__global__ void k_prep(const float* __restrict__ W1, const float* __restrict__ b1,
                       const float* __restrict__ W_out) {
    int i = blockIdx.x;    // 0..255  (row of W1)
    int j = threadIdx.x;   // 0..255
    float v = W1[i * HID + j];
    g_W1T[j * HID + i] = v;

    // block-reduce max|W1 row|
    float m = fabsf(v);
    #pragma unroll
    for (int off = 16; off; off >>= 1) m = fmaxf(m, __shfl_xor_sync(~0u, m, off));
    __shared__ float sm[8];
    int w = j >> 5, l = j & 31;
    if (l == 0) sm[w] = m;
    __syncthreads();
    if (j < 8) {
        float t = sm[j];
        #pragma unroll
        for (int off = 4; off; off >>= 1) t = fmaxf(t, __shfl_xor_sync(0xffu, t, off));
        if (j == 0) atomicMax(&g_wmax_u, __float_as_uint(t));
    }
    if (i == 0) atomicMax(&g_bmax_u, __float_as_uint(fabsf(b1[j])));

    // W_out coord-slice transpose: blocks 0..63 act as m
    if (i < COORD_DIM)
        g_WcT[j * COORD_DIM + i] = W_out[(SPIKE_DIM + i) * HID + j];
}

__global__ void k_finalize() {
    float wmax = __uint_as_float(g_wmax_u);
    float bmax = __uint_as_float(g_bmax_u);
    int hl;
    if (bmax >= 0.995f)      hl = -1;          // everything heavy (safe fallback)
    else if (wmax <= 0.0f)   hl = 1 << 30;     // nothing can spike layer 2
    else                     hl = (int)floorf((0.995f - bmax) / wmax);
    g_Hlim = hl;
}

// ---------------- fused c0 GEMM + light/heavy classifier ----------------
// c0 = [spikes|coords] @ W0^T + b0 ; per row count c0 >= 0.999 -> heavy if > Hlim
#define XS_LD 68
#define WS_LD 260
#define GEMM_SMEM ((64*XS_LD + 64*WS_LD + 256) * 4)

__global__ __launch_bounds__(256, 2)
void k_gemm(const float* __restrict__ spikes, const float* __restrict__ coords,
            const float* __restrict__ W0, const float* __restrict__ b0) {
    extern __shared__ float sh[];
    float* Xs  = sh;                    // [64][XS_LD]  (k-major, transposed)
    float* Ws  = sh + 64 * XS_LD;       // [64][WS_LD]
    float* b0s = Ws + 64 * WS_LD;       // [256]

    int tid = threadIdx.x;
    int tx = tid & 15, ty = tid >> 4;
    int R0 = blockIdx.x * 64;

    b0s[tid] = b0[tid];

    float acc[4][16];
    #pragma unroll
    for (int i = 0; i < 4; i++)
        #pragma unroll
        for (int j = 0; j < 16; j++) acc[i][j] = 0.0f;

    for (int c = 0; c < 3; c++) {
        __syncthreads();
        // ---- load X chunk (64 rows x 64 k), transposed into Xs[k][row]
        const float* xsrc;
        int xstride;
        if (c < 2) { xsrc = spikes + c * 64; xstride = SPIKE_DIM; }
        else       { xsrc = coords;          xstride = COORD_DIM; }
        #pragma unroll
        for (int it = 0; it < 4; it++) {
            int idx = it * 256 + tid;
            int row = idx >> 4, q = idx & 15;
            float4 v = *(const float4*)(xsrc + (size_t)(R0 + row) * xstride + q * 4);
            Xs[(q * 4 + 0) * XS_LD + row] = v.x;
            Xs[(q * 4 + 1) * XS_LD + row] = v.y;
            Xs[(q * 4 + 2) * XS_LD + row] = v.z;
            Xs[(q * 4 + 3) * XS_LD + row] = v.w;
        }
        // ---- load W0 chunk (256 j x 64 k), transposed into Ws[k][j]
        #pragma unroll
        for (int it = 0; it < 16; it++) {
            int idx = it * 256 + tid;
            int j = idx >> 4, q = idx & 15;
            float4 v = *(const float4*)(W0 + (size_t)j * IN_DIM + c * 64 + q * 4);
            Ws[(q * 4 + 0) * WS_LD + j] = v.x;
            Ws[(q * 4 + 1) * WS_LD + j] = v.y;
            Ws[(q * 4 + 2) * WS_LD + j] = v.z;
            Ws[(q * 4 + 3) * WS_LD + j] = v.w;
        }
        __syncthreads();

        #pragma unroll 4
        for (int k = 0; k < 64; k++) {
            float4 a  = *(const float4*)(Xs + k * XS_LD + ty * 4);
            float4 bA = *(const float4*)(Ws + k * WS_LD + tx * 16 + 0);
            float4 bB = *(const float4*)(Ws + k * WS_LD + tx * 16 + 4);
            float4 bC = *(const float4*)(Ws + k * WS_LD + tx * 16 + 8);
            float4 bD = *(const float4*)(Ws + k * WS_LD + tx * 16 + 12);
            float av[4] = {a.x, a.y, a.z, a.w};
            float bv[16] = {bA.x, bA.y, bA.z, bA.w, bB.x, bB.y, bB.z, bB.w,
                            bC.x, bC.y, bC.z, bC.w, bD.x, bD.y, bD.z, bD.w};
            #pragma unroll
            for (int i = 0; i < 4; i++)
                #pragma unroll
                for (int j = 0; j < 16; j++)
                    acc[i][j] = fmaf(av[i], bv[j], acc[i][j]);
        }
    }

    // ---- epilogue: +b0, conservative hot count, classify, spill c0 for heavy rows
    int Hlim = g_Hlim;
    #pragma unroll
    for (int i = 0; i < 4; i++) {
        int cnt = 0;
        #pragma unroll
        for (int j = 0; j < 16; j++) {
            acc[i][j] += b0s[tx * 16 + j];
            cnt += (acc[i][j] >= 0.999f) ? 1 : 0;
        }
        #pragma unroll
        for (int off = 1; off < 16; off <<= 1)
            cnt += __shfl_xor_sync(~0u, cnt, off);   // stays within 16-lane group
        int row = R0 + ty * 4 + i;
        int heavy = (cnt > Hlim) ? 1 : 0;
        if (heavy) {
            float4* dst = (float4*)(g_c0 + (size_t)row * HID + tx * 16);
            dst[0] = make_float4(acc[i][0],  acc[i][1],  acc[i][2],  acc[i][3]);
            dst[1] = make_float4(acc[i][4],  acc[i][5],  acc[i][6],  acc[i][7]);
            dst[2] = make_float4(acc[i][8],  acc[i][9],  acc[i][10], acc[i][11]);
            dst[3] = make_float4(acc[i][12], acc[i][13], acc[i][14], acc[i][15]);
        }
        if (tx == 0) g_flags[row] = heavy;
    }
}

// ---------------- output kernel: warp per row ----------------
__global__ void k_out(const float* __restrict__ b1, const float* __restrict__ b_out,
                      float* __restrict__ out) {
    int gw   = (blockIdx.x * blockDim.x + threadIdx.x) >> 5;
    int lane = threadIdx.x & 31;
    if (gw >= BATCH) return;
    int row = gw;
    float* actp = out + (size_t)row * HID;
    float* crdp = out + (size_t)BATCH * HID + (size_t)row * COORD_DIM;

    int fl = g_flags[row];
    if (!fl) {
        // certified: no layer-2 spikes -> action = 0 exactly, coords = b_out slice exactly
        float4 z = make_float4(0.f, 0.f, 0.f, 0.f);
        ((float4*)actp)[lane]      = z;
        ((float4*)actp)[lane + 32] = z;
        if (lane < 16) {
            float4 cv = *((const float4*)(b_out + SPIKE_DIM) + lane);
            ((float4*)crdp)[lane] = cv;
        }
        return;
    }

    // ---- heavy: exact event-driven simulation (rare) ----
    const float* c0p = g_c0 + (size_t)row * HID;
    float q[8], v0[8], v1[8], b1v[8];
    #pragma unroll
    for (int k = 0; k < 8; k++) {
        q[k]   = OMB * c0p[lane + 32 * k];
        v0[k]  = 0.0f;
        v1[k]  = 0.0f;
        b1v[k] = b1[lane + 32 * k];
    }
    unsigned sp1m[8];
    #pragma unroll
    for (int k = 0; k < 8; k++) sp1m[k] = 0u;

    #pragma unroll 1
    for (int t = 0; t < NUM_STEPS; t++) {
        unsigned act[8];
        #pragma unroll
        for (int k = 0; k < 8; k++) {
            v0[k] = fmaf(BETA, v0[k], q[k]);
            bool sp = (v0[k] >= 1.0f);
            act[k] = __ballot_sync(~0u, sp);
            if (sp) v0[k] = 0.0f;
        }
        float c1[8];
        #pragma unroll
        for (int k = 0; k < 8; k++) c1[k] = b1v[k];
        #pragma unroll
        for (int k = 0; k < 8; k++) {
            unsigned m = act[k];
            while (m) {
                int j = 32 * k + __ffs(m) - 1;
                m &= m - 1;
                const float* wr = g_W1T + (size_t)j * HID;
                #pragma unroll
                for (int r = 0; r < 8; r++) c1[r] += wr[lane + 32 * r];
            }
        }
        #pragma unroll
        for (int k = 0; k < 8; k++) {
            v1[k] = fmaf(BETA, v1[k], OMB * c1[k]);
            bool sp = (v1[k] >= 1.0f);
            unsigned b = __ballot_sync(~0u, sp);
            if (t == NUM_STEPS - 1) sp1m[k] = b;
            if (sp) v1[k] = 0.0f;
        }
    }

    // next_action = final spikes (sign(0/1) == 0/1)
    #pragma unroll
    for (int k = 0; k < 8; k++)
        actp[lane + 32 * k] = ((sp1m[k] >> lane) & 1u) ? 1.0f : 0.0f;

    // next_coords = b_out[128:] + sum over active i of W_out[128+m][i]
    float ca = b_out[SPIKE_DIM + lane];
    float cb = b_out[SPIKE_DIM + 32 + lane];
    #pragma unroll
    for (int k = 0; k < 8; k++) {
        unsigned m = sp1m[k];
        while (m) {
            int i = 32 * k + __ffs(m) - 1;
            m &= m - 1;
            ca += g_WcT[(size_t)i * COORD_DIM + lane];
            cb += g_WcT[(size_t)i * COORD_DIM + 32 + lane];
        }
    }
    crdp[lane]      = ca;
    crdp[lane + 32] = cb;
}

// ---------------- launch ----------------
extern "C" void kernel_launch(void* const* d_in, const int* in_sizes, int n_in,
                              void* d_out, int out_size) {
    const float* spikes = (const float*)d_in[0];
    const float* coords = (const float*)d_in[1];
    const float* W0     = (const float*)d_in[2];
    const float* b0     = (const float*)d_in[3];
    const float* W1     = (const float*)d_in[4];
    const float* b1     = (const float*)d_in[5];
    const float* W_out  = (const float*)d_in[6];
    const float* b_out  = (const float*)d_in[7];
    float* out = (float*)d_out;

    k_init<<<1, 1>>>();
    k_prep<<<256, 256>>>(W1, b1, W_out);
    k_finalize<<<1, 1>>>();

    cudaFuncSetAttribute(k_gemm, cudaFuncAttributeMaxDynamicSharedMemorySize, GEMM_SMEM);
    k_gemm<<<BATCH / 64, 256, GEMM_SMEM>>>(spikes, coords, W0, b0);

    k_out<<<BATCH / 8, 256>>>(b1, b_out, out);
}